// round 2
// baseline (speedup 1.0000x reference)
#include <cuda_runtime.h>
#include <cstdint>
#include <math.h>

#define HH 256
#define WW 256
#define NPIX 65536
#define CCH 32

// ---------------- scratch ----------------
__device__ float g_SQ[2 * NPIX * CCH];   // [b][y][x][c]  fl((s-t)^2), 16 MB (L2-resident)
__device__ float g_D[2 * NPIX];          // reference-ordered patch SSD table
__device__ float g_nnfA[4 * NPIX];       // [b][ch][p]
__device__ float g_nnfB[4 * NPIX];
__device__ float g_dA[2 * NPIX];
__device__ float g_dB[2 * NPIX];

struct RSKeys { uint32_t k[4][2]; };

// ---------------- threefry-2x32 ----------------
__host__ __device__ __forceinline__ uint32_t rotl32(uint32_t v, int d) {
    return (v << d) | (v >> (32 - d));
}

__host__ __device__ __forceinline__ void threefry(uint32_t k0, uint32_t k1,
                                                  uint32_t x0, uint32_t x1,
                                                  uint32_t& o0, uint32_t& o1) {
    uint32_t k2 = k0 ^ k1 ^ 0x1BD11BDAu;
    x0 += k0; x1 += k1;
    x0 += x1; x1 = rotl32(x1, 13); x1 ^= x0;
    x0 += x1; x1 = rotl32(x1, 15); x1 ^= x0;
    x0 += x1; x1 = rotl32(x1, 26); x1 ^= x0;
    x0 += x1; x1 = rotl32(x1, 6);  x1 ^= x0;
    x0 += k1; x1 += k2 + 1u;
    x0 += x1; x1 = rotl32(x1, 17); x1 ^= x0;
    x0 += x1; x1 = rotl32(x1, 29); x1 ^= x0;
    x0 += x1; x1 = rotl32(x1, 16); x1 ^= x0;
    x0 += x1; x1 = rotl32(x1, 24); x1 ^= x0;
    x0 += k2; x1 += k0 + 2u;
    x0 += x1; x1 = rotl32(x1, 13); x1 ^= x0;
    x0 += x1; x1 = rotl32(x1, 15); x1 ^= x0;
    x0 += x1; x1 = rotl32(x1, 26); x1 ^= x0;
    x0 += x1; x1 = rotl32(x1, 6);  x1 ^= x0;
    x0 += k0; x1 += k1 + 3u;
    x0 += x1; x1 = rotl32(x1, 17); x1 ^= x0;
    x0 += x1; x1 = rotl32(x1, 29); x1 ^= x0;
    x0 += x1; x1 = rotl32(x1, 16); x1 ^= x0;
    x0 += x1; x1 = rotl32(x1, 24); x1 ^= x0;
    x0 += k1; x1 += k2 + 4u;
    x0 += x1; x1 = rotl32(x1, 13); x1 ^= x0;
    x0 += x1; x1 = rotl32(x1, 15); x1 ^= x0;
    x0 += x1; x1 = rotl32(x1, 26); x1 ^= x0;
    x0 += x1; x1 = rotl32(x1, 6);  x1 ^= x0;
    x0 += k2; x1 += k0 + 5u;
    o0 = x0; o1 = x1;
}

// partitionable-threefry random bits: element i -> xor of both outputs, counter (0, i)
__device__ __forceinline__ uint32_t rnd32(uint32_t k0, uint32_t k1, uint32_t i) {
    uint32_t o0, o1;
    threefry(k0, k1, 0u, i, o0, o1);
    return o0 ^ o1;
}

// ---------------- float helpers (XLA-matching: NO fma contraction) ----------------
__device__ __forceinline__ float bits_to_f01(uint32_t v) {
    return __fadd_rn(__uint_as_float((v >> 9) | 0x3F800000u), -1.0f);
}

// accurate (correctly-rounded) float log1p via double
__device__ __forceinline__ float log1pf_rn(float a) {
    return (float)log1p((double)a);
}

__device__ __forceinline__ float erfinv_xla(float x) {
    float t = __fmul_rn(x, x);
    float w = -log1pf_rn(-t);
    float p;
    if (w < 5.0f) {
        w = __fadd_rn(w, -2.5f);
        p = 2.81022636e-08f;
        p = __fadd_rn(3.43273939e-07f,  __fmul_rn(p, w));
        p = __fadd_rn(-3.5233877e-06f,  __fmul_rn(p, w));
        p = __fadd_rn(-4.39150654e-06f, __fmul_rn(p, w));
        p = __fadd_rn(0.00021858087f,   __fmul_rn(p, w));
        p = __fadd_rn(-0.00125372503f,  __fmul_rn(p, w));
        p = __fadd_rn(-0.00417768164f,  __fmul_rn(p, w));
        p = __fadd_rn(0.246640727f,     __fmul_rn(p, w));
        p = __fadd_rn(1.50140941f,      __fmul_rn(p, w));
    } else {
        w = __fadd_rn(__fsqrt_rn(w), -3.0f);
        p = -0.000200214257f;
        p = __fadd_rn(0.000100950558f,  __fmul_rn(p, w));
        p = __fadd_rn(0.00134934322f,   __fmul_rn(p, w));
        p = __fadd_rn(-0.00367342844f,  __fmul_rn(p, w));
        p = __fadd_rn(0.00573950773f,   __fmul_rn(p, w));
        p = __fadd_rn(-0.0076224613f,   __fmul_rn(p, w));
        p = __fadd_rn(0.00943887047f,   __fmul_rn(p, w));
        p = __fadd_rn(1.00167406f,      __fmul_rn(p, w));
        p = __fadd_rn(2.83297682f,      __fmul_rn(p, w));
    }
    return __fmul_rn(p, x);
}

__device__ __forceinline__ float normal_from_bits(uint32_t v) {
    float f = bits_to_f01(v);
    // u = f*(hi-lo) + lo; (hi-lo) folds to 2.0f exactly (tie-to-even), lo = -(1-2^-24)
    float u = __fadd_rn(__fmul_rn(f, 2.0f), -0.99999994f);
    u = fmaxf(-0.99999994f, u);
    return __fmul_rn(1.4142135623730951f, erfinv_xla(u));  // rounds to 0x3FB504F3
}

__device__ __forceinline__ float dlookup(int b, float y, float x) {
    int iy = __float2int_rn(y);
    int ix = __float2int_rn(x);
    iy = min(max(iy, 0), HH - 1);
    ix = min(max(ix, 0), WW - 1);
    return g_D[b * NPIX + iy * WW + ix];
}

// ---------------- kernels ----------------
// SQ[b][y][x][c] = fl( fl(S-T)^2 )
__global__ void kSQ(const float* __restrict__ src, const float* __restrict__ tgt) {
    int idx = blockIdx.x * 256 + threadIdx.x;   // (b,p): 0..131071
    int b = idx >> 16;
    int p = idx & 0xFFFF;
    const float* s = src + b * (CCH * NPIX) + p;
    const float* t = tgt + b * (CCH * NPIX) + p;
    float4* dst = reinterpret_cast<float4*>(g_SQ + (size_t)idx * CCH);
#pragma unroll
    for (int c4 = 0; c4 < 8; c4++) {
        float4 v;
        float d0 = __fsub_rn(s[(c4 * 4 + 0) * NPIX], t[(c4 * 4 + 0) * NPIX]);
        float d1 = __fsub_rn(s[(c4 * 4 + 1) * NPIX], t[(c4 * 4 + 1) * NPIX]);
        float d2 = __fsub_rn(s[(c4 * 4 + 2) * NPIX], t[(c4 * 4 + 2) * NPIX]);
        float d3 = __fsub_rn(s[(c4 * 4 + 3) * NPIX], t[(c4 * 4 + 3) * NPIX]);
        v.x = __fmul_rn(d0, d0);
        v.y = __fmul_rn(d1, d1);
        v.z = __fmul_rn(d2, d2);
        v.w = __fmul_rn(d3, d3);
        dst[c4] = v;
    }
}

// D[b][y][x] = strict sequential fp32 sum over (dy, dx, c) of SQ at (y-1+dy, x-1+dx),
// zero-padded (skipping OOB == adding exact 0.0f)
__global__ void kD() {
    int idx = blockIdx.x * 256 + threadIdx.x;
    int b = idx >> 16;
    int p = idx & 0xFFFF;
    int y = p >> 8, x = p & 255;
    float acc = 0.0f;
    for (int dy = -1; dy <= 1; dy++) {
        int yy = y + dy;
        if ((unsigned)yy >= HH) continue;
        for (int dx = -1; dx <= 1; dx++) {
            int xx = x + dx;
            if ((unsigned)xx >= WW) continue;
            const float4* row = reinterpret_cast<const float4*>(
                g_SQ + ((size_t)b * NPIX + yy * WW + xx) * CCH);
#pragma unroll
            for (int c4 = 0; c4 < 8; c4++) {
                float4 v = row[c4];
                acc = __fadd_rn(acc, v.x);
                acc = __fadd_rn(acc, v.y);
                acc = __fadd_rn(acc, v.z);
                acc = __fadd_rn(acc, v.w);
            }
        }
    }
    g_D[idx] = acc;
}

// init nnf = uniform * 255 per (b, ch, p); flat bit index = b*131072 + ch*65536 + p
__global__ void kInit(uint32_t ka, uint32_t kb) {
    int idx = blockIdx.x * 256 + threadIdx.x;   // (b,p)
    int b = idx >> 16;
    int p = idx & 0xFFFF;
    uint32_t iy = (uint32_t)(b * 131072 + p);
    uint32_t ix = iy + 65536u;
    float y = __fmul_rn(bits_to_f01(rnd32(ka, kb, iy)), 255.0f);
    float x = __fmul_rn(bits_to_f01(rnd32(ka, kb, ix)), 255.0f);
    g_nnfA[b * 131072 + p]        = y;
    g_nnfA[b * 131072 + NPIX + p] = x;
    g_dA[b * NPIX + p] = dlookup(b, y, x);
}

// propagate +1: shifted[j] = nnf[j-1]
__global__ void kProp() {
    int idx = blockIdx.x * 256 + threadIdx.x;
    int b = idx >> 16;
    int p = idx & 0xFFFF;
    int i = p >> 8, j = p & 255;
    int pm = (i << 8) | ((j + 255) & 255);
    float cy = g_nnfA[b * 131072 + p];
    float cx = g_nnfA[b * 131072 + NPIX + p];
    float cd = g_dA[b * NPIX + p];
    float sy = g_nnfA[b * 131072 + pm];
    float sx = g_nnfA[b * 131072 + NPIX + pm];
    float sd = g_dA[b * NPIX + pm];
    if (sd < cd) { cy = sy; cx = sx; cd = sd; }
    g_nnfB[b * 131072 + p]        = cy;
    g_nnfB[b * 131072 + NPIX + p] = cx;
    g_dB[b * NPIX + p] = cd;
}

// propagate -1 fused with 4-step random search
__global__ void kRand(float* __restrict__ out, int is_final, RSKeys keys) {
    int idx = blockIdx.x * 256 + threadIdx.x;
    int b = idx >> 16;
    int p = idx & 0xFFFF;
    int i = p >> 8, j = p & 255;
    int pp = (i << 8) | ((j + 1) & 255);

    float y = g_nnfB[b * 131072 + p];
    float x = g_nnfB[b * 131072 + NPIX + p];
    float d = g_dB[b * NPIX + p];
    {
        float sy = g_nnfB[b * 131072 + pp];
        float sx = g_nnfB[b * 131072 + NPIX + pp];
        float sd = g_dB[b * NPIX + pp];
        if (sd < d) { y = sy; x = sx; d = sd; }
    }

    const float scales[4] = {1.0f, 0.5f, 0.25f, 0.125f};
    uint32_t ciy = (uint32_t)(b * 131072 + p);
    uint32_t cix = ciy + 65536u;
#pragma unroll
    for (int s = 0; s < 4; s++) {
        float ny = normal_from_bits(rnd32(keys.k[s][0], keys.k[s][1], ciy));
        float nx = normal_from_bits(rnd32(keys.k[s][0], keys.k[s][1], cix));
        float ry = __fadd_rn(y, __fmul_rn(ny, scales[s]));
        float rx = __fadd_rn(x, __fmul_rn(nx, scales[s]));
        ry = fminf(fmaxf(ry, 0.0f), 255.0f);
        rx = fminf(fmaxf(rx, 0.0f), 255.0f);
        float rd = dlookup(b, ry, rx);
        if (rd < d) { y = ry; x = rx; d = rd; }
    }

    float* dst = is_final ? out : g_nnfA;
    dst[b * 131072 + p]        = y;
    dst[b * 131072 + NPIX + p] = x;
    g_dA[b * NPIX + p] = d;
}

// ---------------- host ----------------
extern "C" void kernel_launch(void* const* d_in, const int* in_sizes, int n_in,
                              void* d_out, int out_size) {
    const float* src = (const float*)d_in[0];
    const float* tgt = (const float*)d_in[1];
    float* out = (float*)d_out;
    (void)in_sizes; (void)n_in; (void)out_size;

    // key(1) = (0,1); foldlike split: child i = both outputs of TF(key, 0, i)
    uint32_t ki0, ki1, kl0, kl1;
    threefry(0u, 1u, 0u, 0u, ki0, ki1);   // k_init
    threefry(0u, 1u, 0u, 1u, kl0, kl1);   // k_loop

    RSKeys keys[5];
    for (uint32_t t = 0; t < 5; t++) {
        uint32_t K0, K1;
        threefry(kl0, kl1, 0u, t, K0, K1);        // fold_in(k_loop, t)
        for (int s = 0; s < 4; s++) {
            uint32_t n0, n1, s0, s1;
            threefry(K0, K1, 0u, 0u, n0, n1);     // next key
            threefry(K0, K1, 0u, 1u, s0, s1);     // k used for normal
            keys[t].k[s][0] = s0;
            keys[t].k[s][1] = s1;
            K0 = n0; K1 = n1;
        }
    }

    kSQ<<<512, 256>>>(src, tgt);
    kD<<<512, 256>>>();
    kInit<<<512, 256>>>(ki0, ki1);
    for (int t = 0; t < 5; t++) {
        kProp<<<512, 256>>>();
        kRand<<<512, 256>>>(out, (t == 4) ? 1 : 0, keys[t]);
    }
}

// round 3
// speedup vs baseline: 7.9653x; 7.9653x over previous
#include <cuda_runtime.h>
#include <cstdint>
#include <math.h>

#define HH 256
#define WW 256
#define NPIX 65536
#define CCH 32

// ---------------- scratch ----------------
__device__ float g_SQ[2 * NPIX * CCH];   // [b][y][x][c]  fl((s-t)^2)
__device__ float g_D[2 * NPIX];          // reference-ordered patch SSD table
__device__ float4 g_s0[2 * NPIX];        // state: (y, x, d, pad)
__device__ float4 g_s1[2 * NPIX];

struct RSKeys { uint32_t k[4][2]; };

// ---------------- threefry-2x32 ----------------
__host__ __device__ __forceinline__ uint32_t rotl32(uint32_t v, int d) {
    return (v << d) | (v >> (32 - d));
}

__host__ __device__ __forceinline__ void threefry(uint32_t k0, uint32_t k1,
                                                  uint32_t x0, uint32_t x1,
                                                  uint32_t& o0, uint32_t& o1) {
    uint32_t k2 = k0 ^ k1 ^ 0x1BD11BDAu;
    x0 += k0; x1 += k1;
    x0 += x1; x1 = rotl32(x1, 13); x1 ^= x0;
    x0 += x1; x1 = rotl32(x1, 15); x1 ^= x0;
    x0 += x1; x1 = rotl32(x1, 26); x1 ^= x0;
    x0 += x1; x1 = rotl32(x1, 6);  x1 ^= x0;
    x0 += k1; x1 += k2 + 1u;
    x0 += x1; x1 = rotl32(x1, 17); x1 ^= x0;
    x0 += x1; x1 = rotl32(x1, 29); x1 ^= x0;
    x0 += x1; x1 = rotl32(x1, 16); x1 ^= x0;
    x0 += x1; x1 = rotl32(x1, 24); x1 ^= x0;
    x0 += k2; x1 += k0 + 2u;
    x0 += x1; x1 = rotl32(x1, 13); x1 ^= x0;
    x0 += x1; x1 = rotl32(x1, 15); x1 ^= x0;
    x0 += x1; x1 = rotl32(x1, 26); x1 ^= x0;
    x0 += x1; x1 = rotl32(x1, 6);  x1 ^= x0;
    x0 += k0; x1 += k1 + 3u;
    x0 += x1; x1 = rotl32(x1, 17); x1 ^= x0;
    x0 += x1; x1 = rotl32(x1, 29); x1 ^= x0;
    x0 += x1; x1 = rotl32(x1, 16); x1 ^= x0;
    x0 += x1; x1 = rotl32(x1, 24); x1 ^= x0;
    x0 += k1; x1 += k2 + 4u;
    x0 += x1; x1 = rotl32(x1, 13); x1 ^= x0;
    x0 += x1; x1 = rotl32(x1, 15); x1 ^= x0;
    x0 += x1; x1 = rotl32(x1, 26); x1 ^= x0;
    x0 += x1; x1 = rotl32(x1, 6);  x1 ^= x0;
    x0 += k2; x1 += k0 + 5u;
    o0 = x0; o1 = x1;
}

__device__ __forceinline__ uint32_t rnd32(uint32_t k0, uint32_t k1, uint32_t i) {
    uint32_t o0, o1;
    threefry(k0, k1, 0u, i, o0, o1);
    return o0 ^ o1;
}

// ---------------- float helpers (XLA-matching: NO fma contraction) ----------------
__device__ __forceinline__ float bits_to_f01(uint32_t v) {
    return __fadd_rn(__uint_as_float((v >> 9) | 0x3F800000u), -1.0f);
}

__device__ __forceinline__ float erfinv_xla(float x) {
    float t = __fmul_rn(x, x);
    float w = -log1pf(-t);                 // float-only, <=1 ulp
    float p;
    if (w < 5.0f) {
        w = __fadd_rn(w, -2.5f);
        p = 2.81022636e-08f;
        p = __fadd_rn(3.43273939e-07f,  __fmul_rn(p, w));
        p = __fadd_rn(-3.5233877e-06f,  __fmul_rn(p, w));
        p = __fadd_rn(-4.39150654e-06f, __fmul_rn(p, w));
        p = __fadd_rn(0.00021858087f,   __fmul_rn(p, w));
        p = __fadd_rn(-0.00125372503f,  __fmul_rn(p, w));
        p = __fadd_rn(-0.00417768164f,  __fmul_rn(p, w));
        p = __fadd_rn(0.246640727f,     __fmul_rn(p, w));
        p = __fadd_rn(1.50140941f,      __fmul_rn(p, w));
    } else {
        w = __fadd_rn(__fsqrt_rn(w), -3.0f);
        p = -0.000200214257f;
        p = __fadd_rn(0.000100950558f,  __fmul_rn(p, w));
        p = __fadd_rn(0.00134934322f,   __fmul_rn(p, w));
        p = __fadd_rn(-0.00367342844f,  __fmul_rn(p, w));
        p = __fadd_rn(0.00573950773f,   __fmul_rn(p, w));
        p = __fadd_rn(-0.0076224613f,   __fmul_rn(p, w));
        p = __fadd_rn(0.00943887047f,   __fmul_rn(p, w));
        p = __fadd_rn(1.00167406f,      __fmul_rn(p, w));
        p = __fadd_rn(2.83297682f,      __fmul_rn(p, w));
    }
    return __fmul_rn(p, x);
}

__device__ __forceinline__ float normal_from_bits(uint32_t v) {
    float f = bits_to_f01(v);
    float u = __fadd_rn(__fmul_rn(f, 2.0f), -0.99999994f);
    u = fmaxf(-0.99999994f, u);
    return __fmul_rn(1.4142135623730951f, erfinv_xla(u));
}

__device__ __forceinline__ float dlookup(int b, float y, float x) {
    int iy = __float2int_rn(y);
    int ix = __float2int_rn(x);
    iy = min(max(iy, 0), HH - 1);
    ix = min(max(ix, 0), WW - 1);
    return __ldg(&g_D[b * NPIX + iy * WW + ix]);
}

// ---------------- kernels ----------------
__global__ void kSQ(const float* __restrict__ src, const float* __restrict__ tgt) {
    int idx = blockIdx.x * 256 + threadIdx.x;
    int b = idx >> 16;
    int p = idx & 0xFFFF;
    const float* s = src + b * (CCH * NPIX) + p;
    const float* t = tgt + b * (CCH * NPIX) + p;
    float4* dst = reinterpret_cast<float4*>(g_SQ + (size_t)idx * CCH);
#pragma unroll
    for (int c4 = 0; c4 < 8; c4++) {
        float4 v;
        float d0 = __fsub_rn(s[(c4 * 4 + 0) * NPIX], t[(c4 * 4 + 0) * NPIX]);
        float d1 = __fsub_rn(s[(c4 * 4 + 1) * NPIX], t[(c4 * 4 + 1) * NPIX]);
        float d2 = __fsub_rn(s[(c4 * 4 + 2) * NPIX], t[(c4 * 4 + 2) * NPIX]);
        float d3 = __fsub_rn(s[(c4 * 4 + 3) * NPIX], t[(c4 * 4 + 3) * NPIX]);
        v.x = __fmul_rn(d0, d0);
        v.y = __fmul_rn(d1, d1);
        v.z = __fmul_rn(d2, d2);
        v.w = __fmul_rn(d3, d3);
        dst[c4] = v;
    }
}

// strict (dy, dx, c) sequential sum, zero-padded
__global__ void kD() {
    int idx = blockIdx.x * 256 + threadIdx.x;
    int b = idx >> 16;
    int p = idx & 0xFFFF;
    int y = p >> 8, x = p & 255;
    float acc = 0.0f;
    for (int dy = -1; dy <= 1; dy++) {
        int yy = y + dy;
        if ((unsigned)yy >= HH) continue;
        for (int dx = -1; dx <= 1; dx++) {
            int xx = x + dx;
            if ((unsigned)xx >= WW) continue;
            const float4* row = reinterpret_cast<const float4*>(
                g_SQ + ((size_t)b * NPIX + yy * WW + xx) * CCH);
#pragma unroll
            for (int c4 = 0; c4 < 8; c4++) {
                float4 v = row[c4];
                acc = __fadd_rn(acc, v.x);
                acc = __fadd_rn(acc, v.y);
                acc = __fadd_rn(acc, v.z);
                acc = __fadd_rn(acc, v.w);
            }
        }
    }
    g_D[idx] = acc;
}

__global__ void kInit(uint32_t ka, uint32_t kb) {
    int idx = blockIdx.x * 256 + threadIdx.x;
    int b = idx >> 16;
    int p = idx & 0xFFFF;
    uint32_t iy = (uint32_t)(b * 131072 + p);
    uint32_t ix = iy + 65536u;
    float y = __fmul_rn(bits_to_f01(rnd32(ka, kb, iy)), 255.0f);
    float x = __fmul_rn(bits_to_f01(rnd32(ka, kb, ix)), 255.0f);
    float4 st;
    st.x = y; st.y = x; st.z = dlookup(b, y, x); st.w = 0.0f;
    g_s0[idx] = st;
}

// One full iteration: propagate(+1) (recomputed for j and j+1), propagate(-1),
// then 4-step random search. flag selects ping-pong direction.
__global__ void kIter(float* __restrict__ out, int flag, int is_final, RSKeys keys) {
    int idx = blockIdx.x * 256 + threadIdx.x;
    int b = idx >> 16;
    int p = idx & 0xFFFF;
    int row = p & 0xFF00;
    int jm = row | ((p + 255) & 255);
    int jp = row | ((p + 1) & 255);

    const float4* rd = flag ? g_s1 : g_s0;
    float4*       wr = flag ? g_s0 : g_s1;

    float4 am = __ldg(&rd[b * NPIX + jm]);
    float4 a0 = __ldg(&rd[b * NPIX + p]);
    float4 ap = __ldg(&rd[b * NPIX + jp]);

    // all 8 normals upfront (pure ALU, independent chains)
    float nrm[8];
    uint32_t ciy = (uint32_t)(b * 131072 + p);
    uint32_t cix = ciy + 65536u;
#pragma unroll
    for (int s = 0; s < 4; s++) {
        nrm[2 * s]     = normal_from_bits(rnd32(keys.k[s][0], keys.k[s][1], ciy));
        nrm[2 * s + 1] = normal_from_bits(rnd32(keys.k[s][0], keys.k[s][1], cix));
    }

    // propagate(+1) at p and p+1, then propagate(-1) at p
    float4 c0 = (am.z < a0.z) ? am : a0;
    float4 c1 = (a0.z < ap.z) ? a0 : ap;
    float4 cur = (c1.z < c0.z) ? c1 : c0;
    float y = cur.x, x = cur.y, d = cur.z;

    const float scales[4] = {1.0f, 0.5f, 0.25f, 0.125f};
#pragma unroll
    for (int s = 0; s < 4; s++) {
        float ry = __fadd_rn(y, __fmul_rn(nrm[2 * s], scales[s]));
        float rx = __fadd_rn(x, __fmul_rn(nrm[2 * s + 1], scales[s]));
        ry = fminf(fmaxf(ry, 0.0f), 255.0f);
        rx = fminf(fmaxf(rx, 0.0f), 255.0f);
        float rdist = dlookup(b, ry, rx);
        if (rdist < d) { y = ry; x = rx; d = rdist; }
    }

    float4 st; st.x = y; st.y = x; st.z = d; st.w = 0.0f;
    wr[b * NPIX + p] = st;
    if (is_final) {
        out[b * 131072 + p]        = y;
        out[b * 131072 + NPIX + p] = x;
    }
}

// ---------------- host ----------------
extern "C" void kernel_launch(void* const* d_in, const int* in_sizes, int n_in,
                              void* d_out, int out_size) {
    const float* src = (const float*)d_in[0];
    const float* tgt = (const float*)d_in[1];
    float* out = (float*)d_out;
    (void)in_sizes; (void)n_in; (void)out_size;

    uint32_t ki0, ki1, kl0, kl1;
    threefry(0u, 1u, 0u, 0u, ki0, ki1);   // k_init
    threefry(0u, 1u, 0u, 1u, kl0, kl1);   // k_loop

    RSKeys keys[5];
    for (uint32_t t = 0; t < 5; t++) {
        uint32_t K0, K1;
        threefry(kl0, kl1, 0u, t, K0, K1);
        for (int s = 0; s < 4; s++) {
            uint32_t n0, n1, s0, s1;
            threefry(K0, K1, 0u, 0u, n0, n1);
            threefry(K0, K1, 0u, 1u, s0, s1);
            keys[t].k[s][0] = s0;
            keys[t].k[s][1] = s1;
            K0 = n0; K1 = n1;
        }
    }

    kSQ<<<512, 256>>>(src, tgt);
    kD<<<512, 256>>>();
    kInit<<<512, 256>>>(ki0, ki1);
    for (int t = 0; t < 5; t++) {
        kIter<<<512, 256>>>(out, t & 1, (t == 4) ? 1 : 0, keys[t]);
    }
}

// round 4
// speedup vs baseline: 9.1779x; 1.1522x over previous
#include <cuda_runtime.h>
#include <cstdint>
#include <math.h>

#define HH 256
#define WW 256
#define NPIX 65536
#define CCH 32

// ---------------- scratch ----------------
__device__ float g_D[2 * NPIX];          // reference-ordered patch SSD table

struct AllKeys { uint32_t k[5][4][2]; };

// ---------------- threefry-2x32 ----------------
__host__ __device__ __forceinline__ uint32_t rotl32(uint32_t v, int d) {
    return (v << d) | (v >> (32 - d));
}

__host__ __device__ __forceinline__ void threefry(uint32_t k0, uint32_t k1,
                                                  uint32_t x0, uint32_t x1,
                                                  uint32_t& o0, uint32_t& o1) {
    uint32_t k2 = k0 ^ k1 ^ 0x1BD11BDAu;
    x0 += k0; x1 += k1;
    x0 += x1; x1 = rotl32(x1, 13); x1 ^= x0;
    x0 += x1; x1 = rotl32(x1, 15); x1 ^= x0;
    x0 += x1; x1 = rotl32(x1, 26); x1 ^= x0;
    x0 += x1; x1 = rotl32(x1, 6);  x1 ^= x0;
    x0 += k1; x1 += k2 + 1u;
    x0 += x1; x1 = rotl32(x1, 17); x1 ^= x0;
    x0 += x1; x1 = rotl32(x1, 29); x1 ^= x0;
    x0 += x1; x1 = rotl32(x1, 16); x1 ^= x0;
    x0 += x1; x1 = rotl32(x1, 24); x1 ^= x0;
    x0 += k2; x1 += k0 + 2u;
    x0 += x1; x1 = rotl32(x1, 13); x1 ^= x0;
    x0 += x1; x1 = rotl32(x1, 15); x1 ^= x0;
    x0 += x1; x1 = rotl32(x1, 26); x1 ^= x0;
    x0 += x1; x1 = rotl32(x1, 6);  x1 ^= x0;
    x0 += k0; x1 += k1 + 3u;
    x0 += x1; x1 = rotl32(x1, 17); x1 ^= x0;
    x0 += x1; x1 = rotl32(x1, 29); x1 ^= x0;
    x0 += x1; x1 = rotl32(x1, 16); x1 ^= x0;
    x0 += x1; x1 = rotl32(x1, 24); x1 ^= x0;
    x0 += k1; x1 += k2 + 4u;
    x0 += x1; x1 = rotl32(x1, 13); x1 ^= x0;
    x0 += x1; x1 = rotl32(x1, 15); x1 ^= x0;
    x0 += x1; x1 = rotl32(x1, 26); x1 ^= x0;
    x0 += x1; x1 = rotl32(x1, 6);  x1 ^= x0;
    x0 += k2; x1 += k0 + 5u;
    o0 = x0; o1 = x1;
}

__device__ __forceinline__ uint32_t rnd32(uint32_t k0, uint32_t k1, uint32_t i) {
    uint32_t o0, o1;
    threefry(k0, k1, 0u, i, o0, o1);
    return o0 ^ o1;
}

// ---------------- float helpers (XLA-matching: NO fma contraction) ----------------
__device__ __forceinline__ float bits_to_f01(uint32_t v) {
    return __fadd_rn(__uint_as_float((v >> 9) | 0x3F800000u), -1.0f);
}

__device__ __forceinline__ float erfinv_xla(float x) {
    float t = __fmul_rn(x, x);
    float w = -log1pf(-t);
    float p;
    if (w < 5.0f) {
        w = __fadd_rn(w, -2.5f);
        p = 2.81022636e-08f;
        p = __fadd_rn(3.43273939e-07f,  __fmul_rn(p, w));
        p = __fadd_rn(-3.5233877e-06f,  __fmul_rn(p, w));
        p = __fadd_rn(-4.39150654e-06f, __fmul_rn(p, w));
        p = __fadd_rn(0.00021858087f,   __fmul_rn(p, w));
        p = __fadd_rn(-0.00125372503f,  __fmul_rn(p, w));
        p = __fadd_rn(-0.00417768164f,  __fmul_rn(p, w));
        p = __fadd_rn(0.246640727f,     __fmul_rn(p, w));
        p = __fadd_rn(1.50140941f,      __fmul_rn(p, w));
    } else {
        w = __fadd_rn(__fsqrt_rn(w), -3.0f);
        p = -0.000200214257f;
        p = __fadd_rn(0.000100950558f,  __fmul_rn(p, w));
        p = __fadd_rn(0.00134934322f,   __fmul_rn(p, w));
        p = __fadd_rn(-0.00367342844f,  __fmul_rn(p, w));
        p = __fadd_rn(0.00573950773f,   __fmul_rn(p, w));
        p = __fadd_rn(-0.0076224613f,   __fmul_rn(p, w));
        p = __fadd_rn(0.00943887047f,   __fmul_rn(p, w));
        p = __fadd_rn(1.00167406f,      __fmul_rn(p, w));
        p = __fadd_rn(2.83297682f,      __fmul_rn(p, w));
    }
    return __fmul_rn(p, x);
}

__device__ __forceinline__ float normal_from_bits(uint32_t v) {
    float f = bits_to_f01(v);
    float u = __fadd_rn(__fmul_rn(f, 2.0f), -0.99999994f);
    u = fmaxf(-0.99999994f, u);
    return __fmul_rn(1.4142135623730951f, erfinv_xla(u));
}

__device__ __forceinline__ float dlookup(int b, float y, float x) {
    int iy = __float2int_rn(y);
    int ix = __float2int_rn(x);
    iy = min(max(iy, 0), HH - 1);
    ix = min(max(ix, 0), WW - 1);
    return __ldg(&g_D[b * NPIX + iy * WW + ix]);
}

// ---------------- kernel 1: fused SQ + D (smem halo tiles) ----------------
// Tile 32x8 pixels, halo 34x10. smem layout channel-major: sq[c][yh][xh],
// index = c*340 + yh*34 + xh  (43520 B). OOB halo entries = exact +0.0f,
// so the strict 288-term (dy, dx, c) fold is bit-identical to zero-padding.
#define TSX 32
#define TSY 8
#define HX 34
#define HY 10
#define HSLOTS (HX * HY)   // 340

__global__ __launch_bounds__(256, 2) void kSQD(const float* __restrict__ src,
                                               const float* __restrict__ tgt) {
    __shared__ float sq[CCH * HSLOTS];
    int tid = threadIdx.x;
    int tileX = blockIdx.x;        // 0..7
    int tileY = blockIdx.y;        // 0..31
    int b     = blockIdx.z;        // 0..1

    int baseY = tileY * TSY - 1;
    int baseX = tileX * TSX - 1;

    // fill: slot A = tid, slot B = tid + 256 (if < 340)
    {
        int j = tid;
        int yh = j / HX, xh = j % HX;
        int gy = baseY + yh, gx = baseX + xh;
        bool inb = ((unsigned)gy < HH) && ((unsigned)gx < WW);
        int gidx = (b * CCH) * NPIX + gy * WW + gx;   // c=0 plane
#pragma unroll
        for (int c = 0; c < CCH; c++) {
            float v = 0.0f;
            if (inb) {
                float d = __fsub_rn(__ldg(&src[gidx + c * NPIX]),
                                    __ldg(&tgt[gidx + c * NPIX]));
                v = __fmul_rn(d, d);
            }
            sq[c * HSLOTS + j] = v;
        }
        int j2 = tid + 256;
        if (j2 < HSLOTS) {
            int yh2 = j2 / HX, xh2 = j2 % HX;
            int gy2 = baseY + yh2, gx2 = baseX + xh2;
            bool inb2 = ((unsigned)gy2 < HH) && ((unsigned)gx2 < WW);
            int gidx2 = (b * CCH) * NPIX + gy2 * WW + gx2;
#pragma unroll
            for (int c = 0; c < CCH; c++) {
                float v = 0.0f;
                if (inb2) {
                    float d = __fsub_rn(__ldg(&src[gidx2 + c * NPIX]),
                                        __ldg(&tgt[gidx2 + c * NPIX]));
                    v = __fmul_rn(d, d);
                }
                sq[c * HSLOTS + j2] = v;
            }
        }
    }
    __syncthreads();

    // strict (dy, dx, c) fold for this thread's pixel
    int tx = tid & 31, ty = tid >> 5;
    float acc = 0.0f;
#pragma unroll
    for (int dy = 0; dy < 3; dy++) {
#pragma unroll
        for (int dx = 0; dx < 3; dx++) {
            const float* pb = &sq[(ty + dy) * HX + (tx + dx)];
#pragma unroll
            for (int c = 0; c < CCH; c++) {
                acc = __fadd_rn(acc, pb[c * HSLOTS]);
            }
        }
    }
    g_D[b * NPIX + (tileY * TSY + ty) * WW + (tileX * TSX + tx)] = acc;
}

// ---------------- kernel 2: init + 5 full PatchMatch iterations ----------------
// Rows are independent under axis-3 roll, so one block owns one (b,row) for
// the whole loop. State exchanged through smem; D gathers hit L2.
__global__ __launch_bounds__(256, 2) void kMatch(float* __restrict__ out,
                                                 uint32_t ka, uint32_t kb,
                                                 AllKeys keys) {
    __shared__ float sy[256], sx[256], sd[256];
    int b   = blockIdx.x >> 8;
    int row = blockIdx.x & 255;
    int t   = threadIdx.x;
    int p   = (row << 8) | t;

    uint32_t ciy = (uint32_t)(b * 131072 + p);
    uint32_t cix = ciy + 65536u;

    float y = __fmul_rn(bits_to_f01(rnd32(ka, kb, ciy)), 255.0f);
    float x = __fmul_rn(bits_to_f01(rnd32(ka, kb, cix)), 255.0f);
    float d = dlookup(b, y, x);

    int tm = (t + 255) & 255;
    int tp = (t + 1) & 255;
    const float scales[4] = {1.0f, 0.5f, 0.25f, 0.125f};

#pragma unroll
    for (int it = 0; it < 5; it++) {
        sy[t] = y; sx[t] = x; sd[t] = d;

        // all 8 normals upfront (independent integer/float chains, needs regs)
        float nrm[8];
#pragma unroll
        for (int s = 0; s < 4; s++) {
            nrm[2 * s]     = normal_from_bits(rnd32(keys.k[it][s][0], keys.k[it][s][1], ciy));
            nrm[2 * s + 1] = normal_from_bits(rnd32(keys.k[it][s][0], keys.k[it][s][1], cix));
        }

        __syncthreads();
        float my = sy[tm], mx = sx[tm], md = sd[tm];
        float qy = sy[tp], qx = sx[tp], qd = sd[tp];
        __syncthreads();   // protect smem before next iteration's writes

        // propagate(+1) at p and p+1, then propagate(-1) at p
        float c0y, c0x, c0d, c1y, c1x, c1d;
        if (md < d) { c0y = my; c0x = mx; c0d = md; } else { c0y = y; c0x = x; c0d = d; }
        if (d < qd) { c1y = y;  c1x = x;  c1d = d;  } else { c1y = qy; c1x = qx; c1d = qd; }
        if (c1d < c0d) { y = c1y; x = c1x; d = c1d; } else { y = c0y; x = c0x; d = c0d; }

        // 4-step random search
#pragma unroll
        for (int s = 0; s < 4; s++) {
            float ry = __fadd_rn(y, __fmul_rn(nrm[2 * s], scales[s]));
            float rx = __fadd_rn(x, __fmul_rn(nrm[2 * s + 1], scales[s]));
            ry = fminf(fmaxf(ry, 0.0f), 255.0f);
            rx = fminf(fmaxf(rx, 0.0f), 255.0f);
            float rd = dlookup(b, ry, rx);
            if (rd < d) { y = ry; x = rx; d = rd; }
        }
    }

    out[b * 131072 + p]        = y;
    out[b * 131072 + NPIX + p] = x;
}

// ---------------- host ----------------
extern "C" void kernel_launch(void* const* d_in, const int* in_sizes, int n_in,
                              void* d_out, int out_size) {
    const float* src = (const float*)d_in[0];
    const float* tgt = (const float*)d_in[1];
    float* out = (float*)d_out;
    (void)in_sizes; (void)n_in; (void)out_size;

    uint32_t ki0, ki1, kl0, kl1;
    threefry(0u, 1u, 0u, 0u, ki0, ki1);   // k_init
    threefry(0u, 1u, 0u, 1u, kl0, kl1);   // k_loop

    AllKeys keys;
    for (uint32_t t = 0; t < 5; t++) {
        uint32_t K0, K1;
        threefry(kl0, kl1, 0u, t, K0, K1);        // fold_in(k_loop, t)
        for (int s = 0; s < 4; s++) {
            uint32_t n0, n1, s0, s1;
            threefry(K0, K1, 0u, 0u, n0, n1);     // next key
            threefry(K0, K1, 0u, 1u, s0, s1);     // key for normal draw
            keys.k[t][s][0] = s0;
            keys.k[t][s][1] = s1;
            K0 = n0; K1 = n1;
        }
    }

    kSQD<<<dim3(8, 32, 2), 256>>>(src, tgt);
    kMatch<<<512, 256>>>(out, ki0, ki1, keys);
}

// round 5
// speedup vs baseline: 14.9481x; 1.6287x over previous
#include <cuda_runtime.h>
#include <cstdint>
#include <math.h>

#define HH 256
#define WW 256
#define NPIX 65536
#define CCH 32

// ---------------- scratch ----------------
__device__ float g_D[2 * NPIX];              // reference-ordered patch SSD table
__device__ float g_N[20 * 4 * NPIX];         // normals: [(it*4+s)][bch][p], 21 MB

struct AllKeys { uint32_t k[5][4][2]; };

// ---------------- threefry-2x32 ----------------
__host__ __device__ __forceinline__ uint32_t rotl32(uint32_t v, int d) {
    return (v << d) | (v >> (32 - d));
}

__host__ __device__ __forceinline__ void threefry(uint32_t k0, uint32_t k1,
                                                  uint32_t x0, uint32_t x1,
                                                  uint32_t& o0, uint32_t& o1) {
    uint32_t k2 = k0 ^ k1 ^ 0x1BD11BDAu;
    x0 += k0; x1 += k1;
    x0 += x1; x1 = rotl32(x1, 13); x1 ^= x0;
    x0 += x1; x1 = rotl32(x1, 15); x1 ^= x0;
    x0 += x1; x1 = rotl32(x1, 26); x1 ^= x0;
    x0 += x1; x1 = rotl32(x1, 6);  x1 ^= x0;
    x0 += k1; x1 += k2 + 1u;
    x0 += x1; x1 = rotl32(x1, 17); x1 ^= x0;
    x0 += x1; x1 = rotl32(x1, 29); x1 ^= x0;
    x0 += x1; x1 = rotl32(x1, 16); x1 ^= x0;
    x0 += x1; x1 = rotl32(x1, 24); x1 ^= x0;
    x0 += k2; x1 += k0 + 2u;
    x0 += x1; x1 = rotl32(x1, 13); x1 ^= x0;
    x0 += x1; x1 = rotl32(x1, 15); x1 ^= x0;
    x0 += x1; x1 = rotl32(x1, 26); x1 ^= x0;
    x0 += x1; x1 = rotl32(x1, 6);  x1 ^= x0;
    x0 += k0; x1 += k1 + 3u;
    x0 += x1; x1 = rotl32(x1, 17); x1 ^= x0;
    x0 += x1; x1 = rotl32(x1, 29); x1 ^= x0;
    x0 += x1; x1 = rotl32(x1, 16); x1 ^= x0;
    x0 += x1; x1 = rotl32(x1, 24); x1 ^= x0;
    x0 += k1; x1 += k2 + 4u;
    x0 += x1; x1 = rotl32(x1, 13); x1 ^= x0;
    x0 += x1; x1 = rotl32(x1, 15); x1 ^= x0;
    x0 += x1; x1 = rotl32(x1, 26); x1 ^= x0;
    x0 += x1; x1 = rotl32(x1, 6);  x1 ^= x0;
    x0 += k2; x1 += k0 + 5u;
    o0 = x0; o1 = x1;
}

__device__ __forceinline__ uint32_t rnd32(uint32_t k0, uint32_t k1, uint32_t i) {
    uint32_t o0, o1;
    threefry(k0, k1, 0u, i, o0, o1);
    return o0 ^ o1;
}

// ---------------- float helpers (XLA-matching: NO fma contraction) ----------------
__device__ __forceinline__ float bits_to_f01(uint32_t v) {
    return __fadd_rn(__uint_as_float((v >> 9) | 0x3F800000u), -1.0f);
}

__device__ __forceinline__ float erfinv_xla(float x) {
    float t = __fmul_rn(x, x);
    float w = -log1pf(-t);
    float p;
    if (w < 5.0f) {
        w = __fadd_rn(w, -2.5f);
        p = 2.81022636e-08f;
        p = __fadd_rn(3.43273939e-07f,  __fmul_rn(p, w));
        p = __fadd_rn(-3.5233877e-06f,  __fmul_rn(p, w));
        p = __fadd_rn(-4.39150654e-06f, __fmul_rn(p, w));
        p = __fadd_rn(0.00021858087f,   __fmul_rn(p, w));
        p = __fadd_rn(-0.00125372503f,  __fmul_rn(p, w));
        p = __fadd_rn(-0.00417768164f,  __fmul_rn(p, w));
        p = __fadd_rn(0.246640727f,     __fmul_rn(p, w));
        p = __fadd_rn(1.50140941f,      __fmul_rn(p, w));
    } else {
        w = __fadd_rn(__fsqrt_rn(w), -3.0f);
        p = -0.000200214257f;
        p = __fadd_rn(0.000100950558f,  __fmul_rn(p, w));
        p = __fadd_rn(0.00134934322f,   __fmul_rn(p, w));
        p = __fadd_rn(-0.00367342844f,  __fmul_rn(p, w));
        p = __fadd_rn(0.00573950773f,   __fmul_rn(p, w));
        p = __fadd_rn(-0.0076224613f,   __fmul_rn(p, w));
        p = __fadd_rn(0.00943887047f,   __fmul_rn(p, w));
        p = __fadd_rn(1.00167406f,      __fmul_rn(p, w));
        p = __fadd_rn(2.83297682f,      __fmul_rn(p, w));
    }
    return __fmul_rn(p, x);
}

__device__ __forceinline__ float normal_from_bits(uint32_t v) {
    float f = bits_to_f01(v);
    float u = __fadd_rn(__fmul_rn(f, 2.0f), -0.99999994f);
    u = fmaxf(-0.99999994f, u);
    return __fmul_rn(1.4142135623730951f, erfinv_xla(u));
}

__device__ __forceinline__ float dlookup(int b, float y, float x) {
    int iy = __float2int_rn(y);
    int ix = __float2int_rn(x);
    iy = min(max(iy, 0), HH - 1);
    ix = min(max(ix, 0), WW - 1);
    return __ldg(&g_D[b * NPIX + iy * WW + ix]);
}

// ---------------- kernel 1: heterogeneous prep ----------------
// blocks [0, 512):    fused SQ + strict-order D via smem halo tiles
// blocks [512, 1536): normal table fill (20 threefry+erfinv per thread)
#define TSX 32
#define TSY 8
#define HX 34
#define HSLOTS (HX * 10)   // 340

__global__ __launch_bounds__(256, 4) void kPrep(const float* __restrict__ src,
                                                const float* __restrict__ tgt,
                                                AllKeys keys) {
    __shared__ float sq[CCH * HSLOTS];   // 43520 B (reserved for all blocks)
    int tid = threadIdx.x;
    int bi  = blockIdx.x;

    if (bi < 512) {
        // ---- SQ + D tile ----
        int tileX = bi & 7;
        int tileY = (bi >> 3) & 31;
        int b     = bi >> 8;
        int baseY = tileY * TSY - 1;
        int baseX = tileX * TSX - 1;

        {
            int j = tid;
            int yh = j / HX, xh = j % HX;
            int gy = baseY + yh, gx = baseX + xh;
            bool inb = ((unsigned)gy < HH) && ((unsigned)gx < WW);
            int gidx = (b * CCH) * NPIX + gy * WW + gx;
#pragma unroll
            for (int c = 0; c < CCH; c++) {
                float v = 0.0f;
                if (inb) {
                    float d = __fsub_rn(__ldg(&src[gidx + c * NPIX]),
                                        __ldg(&tgt[gidx + c * NPIX]));
                    v = __fmul_rn(d, d);
                }
                sq[c * HSLOTS + j] = v;
            }
            int j2 = tid + 256;
            if (j2 < HSLOTS) {
                int yh2 = j2 / HX, xh2 = j2 % HX;
                int gy2 = baseY + yh2, gx2 = baseX + xh2;
                bool inb2 = ((unsigned)gy2 < HH) && ((unsigned)gx2 < WW);
                int gidx2 = (b * CCH) * NPIX + gy2 * WW + gx2;
#pragma unroll
                for (int c = 0; c < CCH; c++) {
                    float v = 0.0f;
                    if (inb2) {
                        float d = __fsub_rn(__ldg(&src[gidx2 + c * NPIX]),
                                            __ldg(&tgt[gidx2 + c * NPIX]));
                        v = __fmul_rn(d, d);
                    }
                    sq[c * HSLOTS + j2] = v;
                }
            }
        }
        __syncthreads();

        int tx = tid & 31, ty = tid >> 5;
        float acc = 0.0f;
#pragma unroll
        for (int dy = 0; dy < 3; dy++) {
#pragma unroll
            for (int dx = 0; dx < 3; dx++) {
                const float* pb = &sq[(ty + dy) * HX + (tx + dx)];
#pragma unroll
                for (int c = 0; c < CCH; c++) {
                    acc = __fadd_rn(acc, pb[c * HSLOTS]);
                }
            }
        }
        g_D[b * NPIX + (tileY * TSY + ty) * WW + (tileX * TSX + tx)] = acc;
    } else {
        // ---- normal table: thread <-> (bch, p), counter = gtid ----
        uint32_t gtid = (uint32_t)((bi - 512) * 256 + tid);   // 0..262143
        for (int it = 0; it < 5; it++) {
#pragma unroll
            for (int s = 0; s < 4; s++) {
                float n = normal_from_bits(
                    rnd32(keys.k[it][s][0], keys.k[it][s][1], gtid));
                g_N[(uint32_t)(it * 4 + s) * 262144u + gtid] = n;
            }
        }
    }
}

// ---------------- kernel 2: init + 5 PatchMatch iterations (light) ----------------
__global__ __launch_bounds__(256, 4) void kMatch(float* __restrict__ out,
                                                 uint32_t ka, uint32_t kb) {
    __shared__ float sy[256], sx[256], sd[256];
    int b   = blockIdx.x >> 8;
    int row = blockIdx.x & 255;
    int t   = threadIdx.x;
    int p   = (row << 8) | t;

    uint32_t ciy = (uint32_t)(b * 131072 + p);
    uint32_t cix = ciy + 65536u;

    float y = __fmul_rn(bits_to_f01(rnd32(ka, kb, ciy)), 255.0f);
    float x = __fmul_rn(bits_to_f01(rnd32(ka, kb, cix)), 255.0f);
    float d = dlookup(b, y, x);

    int tm = (t + 255) & 255;
    int tp = (t + 1) & 255;
    const float scales[4] = {1.0f, 0.5f, 0.25f, 0.125f};

#pragma unroll
    for (int it = 0; it < 5; it++) {
        sy[t] = y; sx[t] = x; sd[t] = d;

        // fetch this iteration's 8 precomputed normals (independent, coalesced)
        float nrm[8];
#pragma unroll
        for (int s = 0; s < 4; s++) {
            uint32_t base = (uint32_t)(it * 4 + s) * 262144u;
            nrm[2 * s]     = __ldg(&g_N[base + ciy]);
            nrm[2 * s + 1] = __ldg(&g_N[base + cix]);
        }

        __syncthreads();
        float my = sy[tm], mx = sx[tm], md = sd[tm];
        float qy = sy[tp], qx = sx[tp], qd = sd[tp];
        __syncthreads();

        // propagate(+1) at p and p+1, then propagate(-1) at p
        float c0y, c0x, c0d, c1y, c1x, c1d;
        if (md < d) { c0y = my; c0x = mx; c0d = md; } else { c0y = y; c0x = x; c0d = d; }
        if (d < qd) { c1y = y;  c1x = x;  c1d = d;  } else { c1y = qy; c1x = qx; c1d = qd; }
        if (c1d < c0d) { y = c1y; x = c1x; d = c1d; } else { y = c0y; x = c0x; d = c0d; }

        // 4-step random search
#pragma unroll
        for (int s = 0; s < 4; s++) {
            float ry = __fadd_rn(y, __fmul_rn(nrm[2 * s], scales[s]));
            float rx = __fadd_rn(x, __fmul_rn(nrm[2 * s + 1], scales[s]));
            ry = fminf(fmaxf(ry, 0.0f), 255.0f);
            rx = fminf(fmaxf(rx, 0.0f), 255.0f);
            float rd = dlookup(b, ry, rx);
            if (rd < d) { y = ry; x = rx; d = rd; }
        }
    }

    out[b * 131072 + p]        = y;
    out[b * 131072 + NPIX + p] = x;
}

// ---------------- host ----------------
extern "C" void kernel_launch(void* const* d_in, const int* in_sizes, int n_in,
                              void* d_out, int out_size) {
    const float* src = (const float*)d_in[0];
    const float* tgt = (const float*)d_in[1];
    float* out = (float*)d_out;
    (void)in_sizes; (void)n_in; (void)out_size;

    uint32_t ki0, ki1, kl0, kl1;
    threefry(0u, 1u, 0u, 0u, ki0, ki1);   // k_init
    threefry(0u, 1u, 0u, 1u, kl0, kl1);   // k_loop

    AllKeys keys;
    for (uint32_t t = 0; t < 5; t++) {
        uint32_t K0, K1;
        threefry(kl0, kl1, 0u, t, K0, K1);        // fold_in(k_loop, t)
        for (int s = 0; s < 4; s++) {
            uint32_t n0, n1, s0, s1;
            threefry(K0, K1, 0u, 0u, n0, n1);     // next key
            threefry(K0, K1, 0u, 1u, s0, s1);     // key for normal draw
            keys.k[t][s][0] = s0;
            keys.k[t][s][1] = s1;
            K0 = n0; K1 = n1;
        }
    }

    kPrep<<<1536, 256>>>(src, tgt, keys);
    kMatch<<<512, 256>>>(out, ki0, ki1);
}